// round 1
// baseline (speedup 1.0000x reference)
#include <cuda_runtime.h>
#include <math.h>

#define NN   100000
#define EE   1600000
#define ET   (EE + NN)      // edges + self loops
#define XS   52             // padded row stride (16B-aligned rows: 52*4=208)
#define DIN  25
#define DOUT 50

// ---------------- scratch (device globals; zero-init .bss) ----------------
__device__ float g_xl[3][NN * XS];   // source transforms (pads stay 0 forever)
__device__ float g_xr[3][NN * XS];   // target transforms
__device__ float g_out[3][NN * XS];  // aggregation accumulators (zeroed per launch)
__device__ float g_e[3][ET];         // exp(score) per edge
__device__ float g_sum[3][NN];       // softmax denominators (zeroed per launch)
__device__ float g_Wc[150 * 75];     // folded proj_W @ cls_W1
__device__ float g_bc[75];           // folded bias

// ---------------- zero accumulators ----------------
__global__ void k_zero() {
    long long stride = (long long)gridDim.x * blockDim.x;
    long long i = (long long)blockIdx.x * blockDim.x + threadIdx.x;
    long long tot4 = (3LL * NN * XS) / 4;
    float4 z = make_float4(0.f, 0.f, 0.f, 0.f);
    for (long long p = i; p < tot4; p += stride)
        reinterpret_cast<float4*>(&g_out[0][0])[p] = z;
    for (long long p = i; p < 3LL * NN; p += stride)
        (&g_sum[0][0])[p] = 0.f;
}

// ---------------- fold proj_W @ cls_W1 (no activation between them) -------
__global__ void k_fold(const float* __restrict__ P, const float* __restrict__ pb,
                       const float* __restrict__ W1, const float* __restrict__ b1) {
    int idx = blockIdx.x * blockDim.x + threadIdx.x;
    if (idx < 150 * 75) {
        int k = idx / 75, j = idx % 75;
        float a = 0.f;
        for (int m = 0; m < 150; m++) a += P[k * 150 + m] * W1[m * 75 + j];
        g_Wc[idx] = a;
    } else if (idx < 150 * 75 + 75) {
        int j = idx - 150 * 75;
        float a = b1[j];
        for (int m = 0; m < 150; m++) a += pb[m] * W1[m * 75 + j];
        g_bc[j] = a;
    }
}

// ---------------- node transforms: xl/xr for all 3 tags --------------------
__global__ void k1(const float* __restrict__ x,
                   const float* __restrict__ Wl0, const float* __restrict__ bl0,
                   const float* __restrict__ Wr0, const float* __restrict__ br0,
                   const float* __restrict__ Wl1, const float* __restrict__ bl1,
                   const float* __restrict__ Wr1, const float* __restrict__ br1,
                   const float* __restrict__ Wl2, const float* __restrict__ bl2,
                   const float* __restrict__ Wr2, const float* __restrict__ br2) {
    __shared__ float sW[6][DIN * DOUT];
    __shared__ float sb[6][DOUT];
    {
        const float* Ws[6] = {Wl0, Wr0, Wl1, Wr1, Wl2, Wr2};
        const float* bs[6] = {bl0, br0, bl1, br1, bl2, br2};
        for (int w = 0; w < 6; w++) {
            for (int i = threadIdx.x; i < DIN * DOUT; i += blockDim.x) sW[w][i] = Ws[w][i];
            for (int i = threadIdx.x; i < DOUT; i += blockDim.x) sb[w][i] = bs[w][i];
        }
    }
    __syncthreads();
    int n = blockIdx.x * blockDim.x + threadIdx.x;
    if (n >= NN) return;

    float xv[DIN];
#pragma unroll
    for (int k = 0; k < DIN; k++) xv[k] = x[n * DIN + k];

    for (int w = 0; w < 6; w++) {
        int t = w >> 1;
        float* dst = (w & 1) ? &g_xr[t][n * XS] : &g_xl[t][n * XS];
        const float* Wp = sW[w];
        const float* bp = sb[w];
        for (int j4 = 0; j4 < 48; j4 += 4) {
            float a0 = bp[j4], a1 = bp[j4 + 1], a2 = bp[j4 + 2], a3 = bp[j4 + 3];
#pragma unroll
            for (int k = 0; k < DIN; k++) {
                float xk = xv[k];
                const float* wr = &Wp[k * DOUT + j4];
                a0 += xk * wr[0]; a1 += xk * wr[1]; a2 += xk * wr[2]; a3 += xk * wr[3];
            }
            *reinterpret_cast<float4*>(dst + j4) = make_float4(a0, a1, a2, a3);
        }
        float a0 = bp[48], a1 = bp[49];
#pragma unroll
        for (int k = 0; k < DIN; k++) {
            float xk = xv[k];
            a0 += xk * Wp[k * DOUT + 48];
            a1 += xk * Wp[k * DOUT + 49];
        }
        *reinterpret_cast<float2*>(dst + 48) = make_float2(a0, a1);
    }
}

// ---------------- edge scores -> e = exp(score), denominator atomics -------
// warp per edge: lanes 0..31 own dims d and d+32 (d+32 only for lane<18)
__global__ void k2(int tag, const int* __restrict__ ei, const float* __restrict__ att) {
    int gw = (blockIdx.x * blockDim.x + threadIdx.x) >> 5;
    int lane = threadIdx.x & 31;
    if (gw >= ET) return;
    int src, dst;
    if (gw < EE) { src = __ldg(ei + gw); dst = __ldg(ei + EE + gw); }
    else         { src = gw - EE; dst = src; }

    const float* xl = &g_xl[tag][src * XS];
    const float* xr = &g_xr[tag][dst * XS];

    float a = xl[lane] + xr[lane];
    float m = a > 0.f ? a : 0.2f * a;
    float s = m * __ldg(att + lane);
    if (lane < 18) {
        float a2 = xl[lane + 32] + xr[lane + 32];
        float m2 = a2 > 0.f ? a2 : 0.2f * a2;
        s += m2 * __ldg(att + lane + 32);
    }
#pragma unroll
    for (int o = 16; o; o >>= 1) s += __shfl_down_sync(0xffffffffu, s, o);
    if (lane == 0) {
        float e = expf(s);  // scores are O(8): no max-subtraction needed
        g_e[tag][gw] = e;
        atomicAdd(&g_sum[tag][dst], e);
    }
}

// ---------------- aggregation: out[dst] += alpha * xl[src] -----------------
// 2 edges per warp; 13 lanes per edge each handle one float4 chunk via red.v4
__global__ void k3(int tag, const int* __restrict__ ei) {
    int gw = (blockIdx.x * blockDim.x + threadIdx.x) >> 5;
    int lane = threadIdx.x & 31;
    int grp = lane >> 4, c = lane & 15;
    long long idx = (long long)gw * 2 + grp;
    if (idx >= ET || c >= 13) return;

    int src, dst;
    if (idx < EE) { src = __ldg(ei + idx); dst = __ldg(ei + EE + idx); }
    else          { src = (int)(idx - EE); dst = src; }

    float e = g_e[tag][idx];
    float ssum = g_sum[tag][dst];
    float alpha = e / (ssum + 1e-16f);

    const float4 v = *reinterpret_cast<const float4*>(&g_xl[tag][src * XS + c * 4]);
    float* p = &g_out[tag][dst * XS + c * 4];
    asm volatile("red.global.add.v4.f32 [%0], {%1,%2,%3,%4};"
                 :: "l"(p), "f"(v.x * alpha), "f"(v.y * alpha),
                    "f"(v.z * alpha), "f"(v.w * alpha)
                 : "memory");
}

// ---------------- fused head: leaky(out+bo) -> folded 150x75 -> 75x30 -> 30x2
__global__ void k4(const float* __restrict__ bo_p, const float* __restrict__ bo_s,
                   const float* __restrict__ bo_v,
                   const float* __restrict__ W2, const float* __restrict__ b2,
                   const float* __restrict__ W3, const float* __restrict__ b3,
                   float* __restrict__ out) {
    extern __shared__ float sm[];
    float* sWc  = sm;                 // 11250
    float* sbc  = sWc + 11250;        // 75
    float* sW2  = sbc + 75;           // 2250
    float* sb2  = sW2 + 2250;         // 30
    float* sW3  = sb2 + 30;           // 60
    float* sb3  = sW3 + 60;           // 2
    float* tile = sb3 + 2;            // 128 * 161 (odd stride: conflict-free)

    int tid = threadIdx.x;
    for (int i = tid; i < 11250; i += 128) sWc[i] = g_Wc[i];
    for (int i = tid; i < 75;    i += 128) sbc[i] = g_bc[i];
    for (int i = tid; i < 2250;  i += 128) sW2[i] = W2[i];
    if (tid < 30) sb2[tid] = b2[tid];
    if (tid < 60) sW3[tid] = W3[tid];
    if (tid < 2)  sb3[tid] = b3[tid];

    int nb = blockIdx.x * 128;
    const float* bos[3] = {bo_p, bo_s, bo_v};
    for (int t = 0; t < 3; t++) {
        for (int idx = tid; idx < 128 * 50; idx += 128) {
            int r = idx / 50, c = idx % 50;
            int n = nb + r;
            float v = 0.f;
            if (n < NN) v = g_out[t][n * XS + c] + __ldg(&bos[t][c]);
            tile[r * 161 + t * 50 + c] = v > 0.f ? v : 0.1f * v;
        }
    }
    __syncthreads();

    int n = nb + tid;
    if (n >= NN) return;

    float acc2[75];
#pragma unroll
    for (int j = 0; j < 75; j++) acc2[j] = sbc[j];
    const float* hrow = &tile[tid * 161];
    for (int k = 0; k < 150; k++) {
        float hk = hrow[k];
        const float* wr = &sWc[k * 75];
#pragma unroll
        for (int j = 0; j < 75; j++) acc2[j] += hk * wr[j];
    }
    // leaky(0.1) and stash back into own tile row (enables dynamic indexing)
    float* h2 = &tile[tid * 161];
#pragma unroll
    for (int j = 0; j < 75; j++) { float v = acc2[j]; h2[j] = v > 0.f ? v : 0.1f * v; }

    float acc3[30];
#pragma unroll
    for (int j = 0; j < 30; j++) acc3[j] = sb2[j];
    for (int k = 0; k < 75; k++) {
        float hk = h2[k];
        const float* wr = &sW2[k * 30];
#pragma unroll
        for (int j = 0; j < 30; j++) acc3[j] += hk * wr[j];
    }

    float o0 = sb3[0], o1 = sb3[1];
#pragma unroll
    for (int k = 0; k < 30; k++) {
        float v = acc3[k];
        v = v > 0.f ? v : 0.1f * v;
        o0 += v * sW3[k * 2];
        o1 += v * sW3[k * 2 + 1];
    }
    out[n * 2]     = o0;
    out[n * 2 + 1] = o1;
}

// ---------------- launch -----------------------------------------------------
extern "C" void kernel_launch(void* const* d_in, const int* in_sizes, int n_in,
                              void* d_out, int out_size) {
    const float* x    = (const float*)d_in[0];
    const int*   eis[3] = {(const int*)d_in[1], (const int*)d_in[2], (const int*)d_in[3]};
    const float *Wl[3], *bl[3], *Wr[3], *br[3], *att[3], *bo[3];
    int i = 4;
    for (int t = 0; t < 3; t++) {
        Wl[t]  = (const float*)d_in[i++];
        bl[t]  = (const float*)d_in[i++];
        Wr[t]  = (const float*)d_in[i++];
        br[t]  = (const float*)d_in[i++];
        att[t] = (const float*)d_in[i++];
        bo[t]  = (const float*)d_in[i++];
    }
    const float* proj_W = (const float*)d_in[22];
    const float* proj_b = (const float*)d_in[23];
    const float* cls_W1 = (const float*)d_in[24];
    const float* cls_b1 = (const float*)d_in[25];
    const float* cls_W2 = (const float*)d_in[26];
    const float* cls_b2 = (const float*)d_in[27];
    const float* cls_W3 = (const float*)d_in[28];
    const float* cls_b3 = (const float*)d_in[29];
    float* out = (float*)d_out;

    const int SMEM_K4 = (11250 + 75 + 2250 + 30 + 60 + 2 + 128 * 161) * 4;  // 137100 B
    cudaFuncSetAttribute(k4, cudaFuncAttributeMaxDynamicSharedMemorySize, SMEM_K4);

    k_zero<<<2048, 256>>>();
    k_fold<<<(150 * 75 + 75 + 127) / 128, 128>>>(proj_W, proj_b, cls_W1, cls_b1);
    k1<<<(NN + 127) / 128, 128>>>(x,
                                  Wl[0], bl[0], Wr[0], br[0],
                                  Wl[1], bl[1], Wr[1], br[1],
                                  Wl[2], bl[2], Wr[2], br[2]);
    for (int t = 0; t < 3; t++)
        k2<<<ET / 8, 256>>>(t, eis[t], att[t]);   // warp per edge, 8 warps/block
    for (int t = 0; t < 3; t++)
        k3<<<ET / 16, 256>>>(t, eis[t]);          // 2 edges per warp
    k4<<<(NN + 127) / 128, 128, SMEM_K4>>>(bo[0], bo[1], bo[2],
                                           cls_W2, cls_b2, cls_W3, cls_b3, out);
}

// round 2
// speedup vs baseline: 1.4106x; 1.4106x over previous
#include <cuda_runtime.h>
#include <math.h>

#define NN   100000
#define EE   1600000
#define ET   (EE + NN)      // edges + self loops per tag
#define E3   (3LL * ET)     // all tags
#define XS   52             // padded row stride (52*4 = 208B, 16B-aligned)
#define DIN  25
#define DOUT 50

// ---------------- scratch (device globals) ----------------
__device__ float g_xl[3][NN * XS];   // source transforms (pads never written -> stay 0)
__device__ float g_xr[3][NN * XS];   // target transforms
__device__ float g_out[3][NN * XS];  // UNNORMALIZED numerators (zeroed per launch)
__device__ float g_sum[3][NN];       // softmax denominators (zeroed per launch)
__device__ float g_att[3][64];       // zero-padded attention vectors
__device__ float g_Wc[150 * 75];     // folded proj_W @ cls_W1
__device__ float g_bc[75];           // folded bias

// ---------------- zero accumulators + stage padded att --------------------
__global__ void k_zero(const float* __restrict__ att0, const float* __restrict__ att1,
                       const float* __restrict__ att2) {
    long long stride = (long long)gridDim.x * blockDim.x;
    long long i = (long long)blockIdx.x * blockDim.x + threadIdx.x;
    long long tot4 = (3LL * NN * XS) / 4;
    float4 z = make_float4(0.f, 0.f, 0.f, 0.f);
    for (long long p = i; p < tot4; p += stride)
        reinterpret_cast<float4*>(&g_out[0][0])[p] = z;
    for (long long p = i; p < 3LL * NN; p += stride)
        (&g_sum[0][0])[p] = 0.f;
    if (i < 3 * 64) {
        int t = (int)(i >> 6), c = (int)(i & 63);
        const float* a = t == 0 ? att0 : (t == 1 ? att1 : att2);
        g_att[t][c] = c < DOUT ? a[c] : 0.f;
    }
}

// ---------------- fold proj_W @ cls_W1 (no activation between) ------------
__global__ void k_fold(const float* __restrict__ P, const float* __restrict__ pb,
                       const float* __restrict__ W1, const float* __restrict__ b1) {
    int idx = blockIdx.x * blockDim.x + threadIdx.x;
    if (idx < 150 * 75) {
        int k = idx / 75, j = idx % 75;
        float a = 0.f;
        for (int m = 0; m < 150; m++) a += P[k * 150 + m] * W1[m * 75 + j];
        g_Wc[idx] = a;
    } else if (idx < 150 * 75 + 75) {
        int j = idx - 150 * 75;
        float a = b1[j];
        for (int m = 0; m < 150; m++) a += pb[m] * W1[m * 75 + j];
        g_bc[j] = a;
    }
}

// ---------------- node transforms: xl/xr for all 3 tags --------------------
__global__ void k1(const float* __restrict__ x,
                   const float* __restrict__ Wl0, const float* __restrict__ bl0,
                   const float* __restrict__ Wr0, const float* __restrict__ br0,
                   const float* __restrict__ Wl1, const float* __restrict__ bl1,
                   const float* __restrict__ Wr1, const float* __restrict__ br1,
                   const float* __restrict__ Wl2, const float* __restrict__ bl2,
                   const float* __restrict__ Wr2, const float* __restrict__ br2) {
    __shared__ float sW[6][DIN * DOUT];
    __shared__ float sb[6][DOUT];
    {
        const float* Ws[6] = {Wl0, Wr0, Wl1, Wr1, Wl2, Wr2};
        const float* bs[6] = {bl0, br0, bl1, br1, bl2, br2};
        for (int w = 0; w < 6; w++) {
            for (int i = threadIdx.x; i < DIN * DOUT; i += blockDim.x) sW[w][i] = Ws[w][i];
            for (int i = threadIdx.x; i < DOUT; i += blockDim.x) sb[w][i] = bs[w][i];
        }
    }
    __syncthreads();
    int n = blockIdx.x * blockDim.x + threadIdx.x;
    if (n >= NN) return;

    float xv[DIN];
#pragma unroll
    for (int k = 0; k < DIN; k++) xv[k] = x[n * DIN + k];

    for (int w = 0; w < 6; w++) {
        int t = w >> 1;
        float* dst = (w & 1) ? &g_xr[t][n * XS] : &g_xl[t][n * XS];
        const float* Wp = sW[w];
        const float* bp = sb[w];
        for (int j4 = 0; j4 < 48; j4 += 4) {
            float a0 = bp[j4], a1 = bp[j4 + 1], a2 = bp[j4 + 2], a3 = bp[j4 + 3];
#pragma unroll
            for (int k = 0; k < DIN; k++) {
                float xk = xv[k];
                const float* wr = &Wp[k * DOUT + j4];
                a0 += xk * wr[0]; a1 += xk * wr[1]; a2 += xk * wr[2]; a3 += xk * wr[3];
            }
            *reinterpret_cast<float4*>(dst + j4) = make_float4(a0, a1, a2, a3);
        }
        float a0 = bp[48], a1 = bp[49];
#pragma unroll
        for (int k = 0; k < DIN; k++) {
            float xk = xv[k];
            a0 += xk * Wp[k * DOUT + 48];
            a1 += xk * Wp[k * DOUT + 49];
        }
        *reinterpret_cast<float2*>(dst + 48) = make_float2(a0, a1);
    }
}

// ---------------- fused edge pass: score -> e -> unnormalized aggregate ----
// 2 edges per warp (one per 16-lane half). Lanes c<13 each own a float4 chunk.
// Per edge: 2x LDG.128, ~8 FFMA, 4 butterfly shuffles, 1 exp, 1 RED.v4, 1 atomic.
__global__ void __launch_bounds__(256) k23(const int* __restrict__ ei0,
                                           const int* __restrict__ ei1,
                                           const int* __restrict__ ei2) {
    long long gw = ((long long)blockIdx.x * blockDim.x + threadIdx.x) >> 5;
    int lane = threadIdx.x & 31;
    int c = lane & 15;
    long long eg = gw * 2 + (lane >> 4);          // global edge id for this half
    bool valid = eg < E3;
    int tag = eg >= 2LL * ET ? 2 : (eg >= ET ? 1 : 0);
    int idx = (int)(eg - (long long)tag * ET);

    int src = 0, dst = 0;
    if (valid) {
        const int* ei = tag == 0 ? ei0 : (tag == 1 ? ei1 : ei2);
        if (idx < EE) { src = __ldg(ei + idx); dst = __ldg(ei + EE + idx); }
        else          { src = idx - EE; dst = src; }
    }

    float4 v = make_float4(0.f, 0.f, 0.f, 0.f);
    float s = 0.f;
    if (valid && c < 13) {
        v = __ldg(reinterpret_cast<const float4*>(&g_xl[tag][src * XS]) + c);
        float4 w = __ldg(reinterpret_cast<const float4*>(&g_xr[tag][dst * XS]) + c);
        const float4 at = *reinterpret_cast<const float4*>(&g_att[tag][c * 4]);
        float a;
        a = v.x + w.x; a = a > 0.f ? a : 0.2f * a; s  = a * at.x;
        a = v.y + w.y; a = a > 0.f ? a : 0.2f * a; s += a * at.y;
        a = v.z + w.z; a = a > 0.f ? a : 0.2f * a; s += a * at.z;
        a = v.w + w.w; a = a > 0.f ? a : 0.2f * a; s += a * at.w;
    }
    // butterfly over the 16-lane half: every lane ends with the full sum
#pragma unroll
    for (int o = 8; o; o >>= 1) s += __shfl_xor_sync(0xffffffffu, s, o, 16);

    if (!valid) return;
    float e = __expf(s);  // scores are O(10): no max-subtraction needed

    if (c < 13) {
        float* p = &g_out[tag][dst * XS + c * 4];
        asm volatile("red.global.add.v4.f32 [%0], {%1,%2,%3,%4};"
                     :: "l"(p), "f"(v.x * e), "f"(v.y * e),
                        "f"(v.z * e), "f"(v.w * e)
                     : "memory");
    }
    if (c == 0) atomicAdd(&g_sum[tag][dst], e);
}

// ---------------- fused head: normalize -> leaky -> folded MLP -------------
__global__ void k4(const float* __restrict__ bo_p, const float* __restrict__ bo_s,
                   const float* __restrict__ bo_v,
                   const float* __restrict__ W2, const float* __restrict__ b2,
                   const float* __restrict__ W3, const float* __restrict__ b3,
                   float* __restrict__ out) {
    extern __shared__ float sm[];
    float* sWc  = sm;                 // 11250
    float* sbc  = sWc + 11250;        // 75
    float* sW2  = sbc + 75;           // 2250
    float* sb2  = sW2 + 2250;         // 30
    float* sW3  = sb2 + 30;           // 60
    float* sb3  = sW3 + 60;           // 2
    float* tile = sb3 + 2;            // 128 * 161 (odd stride: conflict-free)

    int tid = threadIdx.x;
    for (int i = tid; i < 11250; i += 128) sWc[i] = g_Wc[i];
    for (int i = tid; i < 75;    i += 128) sbc[i] = g_bc[i];
    for (int i = tid; i < 2250;  i += 128) sW2[i] = W2[i];
    if (tid < 30) sb2[tid] = b2[tid];
    if (tid < 60) sW3[tid] = W3[tid];
    if (tid < 2)  sb3[tid] = b3[tid];

    int nb = blockIdx.x * 128;
    const float* bos[3] = {bo_p, bo_s, bo_v};
    for (int t = 0; t < 3; t++) {
        for (int idx = tid; idx < 128 * 50; idx += 128) {
            int r = idx / 50, cc = idx % 50;
            int n = nb + r;
            float v = 0.f;
            if (n < NN) {
                float inv = 1.f / (g_sum[t][n] + 1e-16f);
                v = g_out[t][n * XS + cc] * inv + __ldg(&bos[t][cc]);
            }
            tile[r * 161 + t * 50 + cc] = v > 0.f ? v : 0.1f * v;
        }
    }
    __syncthreads();

    int n = nb + tid;
    if (n >= NN) return;

    float acc2[75];
#pragma unroll
    for (int j = 0; j < 75; j++) acc2[j] = sbc[j];
    const float* hrow = &tile[tid * 161];
    for (int k = 0; k < 150; k++) {
        float hk = hrow[k];
        const float* wr = &sWc[k * 75];
#pragma unroll
        for (int j = 0; j < 75; j++) acc2[j] += hk * wr[j];
    }
    float* h2 = &tile[tid * 161];
#pragma unroll
    for (int j = 0; j < 75; j++) { float v = acc2[j]; h2[j] = v > 0.f ? v : 0.1f * v; }

    float acc3[30];
#pragma unroll
    for (int j = 0; j < 30; j++) acc3[j] = sb2[j];
    for (int k = 0; k < 75; k++) {
        float hk = h2[k];
        const float* wr = &sW2[k * 30];
#pragma unroll
        for (int j = 0; j < 30; j++) acc3[j] += hk * wr[j];
    }

    float o0 = sb3[0], o1 = sb3[1];
#pragma unroll
    for (int k = 0; k < 30; k++) {
        float v = acc3[k];
        v = v > 0.f ? v : 0.1f * v;
        o0 += v * sW3[k * 2];
        o1 += v * sW3[k * 2 + 1];
    }
    out[n * 2]     = o0;
    out[n * 2 + 1] = o1;
}

// ---------------- launch -----------------------------------------------------
extern "C" void kernel_launch(void* const* d_in, const int* in_sizes, int n_in,
                              void* d_out, int out_size) {
    const float* x    = (const float*)d_in[0];
    const int*   eis[3] = {(const int*)d_in[1], (const int*)d_in[2], (const int*)d_in[3]};
    const float *Wl[3], *bl[3], *Wr[3], *br[3], *att[3], *bo[3];
    int i = 4;
    for (int t = 0; t < 3; t++) {
        Wl[t]  = (const float*)d_in[i++];
        bl[t]  = (const float*)d_in[i++];
        Wr[t]  = (const float*)d_in[i++];
        br[t]  = (const float*)d_in[i++];
        att[t] = (const float*)d_in[i++];
        bo[t]  = (const float*)d_in[i++];
    }
    const float* proj_W = (const float*)d_in[22];
    const float* proj_b = (const float*)d_in[23];
    const float* cls_W1 = (const float*)d_in[24];
    const float* cls_b1 = (const float*)d_in[25];
    const float* cls_W2 = (const float*)d_in[26];
    const float* cls_b2 = (const float*)d_in[27];
    const float* cls_W3 = (const float*)d_in[28];
    const float* cls_b3 = (const float*)d_in[29];
    float* out = (float*)d_out;

    const int SMEM_K4 = (11250 + 75 + 2250 + 30 + 60 + 2 + 128 * 161) * 4;  // 137100 B
    cudaFuncSetAttribute(k4, cudaFuncAttributeMaxDynamicSharedMemorySize, SMEM_K4);

    k_zero<<<2048, 256>>>(att[0], att[1], att[2]);
    k_fold<<<(150 * 75 + 75 + 127) / 128, 128>>>(proj_W, proj_b, cls_W1, cls_b1);
    k1<<<(NN + 127) / 128, 128>>>(x,
                                  Wl[0], bl[0], Wr[0], br[0],
                                  Wl[1], bl[1], Wr[1], br[1],
                                  Wl[2], bl[2], Wr[2], br[2]);
    // fused edge pass over all 3 tags: 2 edges per warp
    long long warps = (E3 + 1) / 2;
    long long blocks = (warps * 32 + 255) / 256;
    k23<<<(unsigned)blocks, 256>>>(eis[0], eis[1], eis[2]);
    k4<<<(NN + 127) / 128, 128, SMEM_K4>>>(bo[0], bo[1], bo[2],
                                           cls_W2, cls_b2, cls_W3, cls_b3, out);
}

// round 3
// speedup vs baseline: 1.9506x; 1.3829x over previous
#include <cuda_runtime.h>
#include <math.h>

#define NN   100000
#define N3   (3 * NN)
#define EE   1600000
#define E3   (3 * EE)
#define XS   52              // padded row stride (52*4 = 208B)
#define XS4  13              // row stride in float4
#define DIN  25
#define DOUT 50
#define SBLK 512
#define NSB  ((N3 + SBLK - 1) / SBLK)   // 586

// ---------------- scratch (device globals) ----------------
__device__ __align__(16) float g_xl[3 * NN * XS];   // source transforms (pads stay 0)
__device__ __align__(16) float g_xr[3 * NN * XS];   // target transforms
__device__ __align__(16) float g_out[3 * NN * XS];  // unnormalized numerators (fully overwritten)
__device__ float g_sum[N3];          // softmax denominators (fully overwritten)
__device__ float g_att[3][64];       // zero-padded attention vectors
__device__ float g_Wc[150 * 75];     // folded proj_W @ cls_W1
__device__ float g_bc[75];
__device__ int   g_cnt[N3];          // histogram, then scatter cursor
__device__ int   g_off[N3];          // CSR offsets
__device__ int   g_srcs[E3];         // dst-sorted source ids
__device__ int   g_part[1024];       // scan partials

// ---------------- init: zero histogram + stage padded att ------------------
__global__ void k_init(const float* __restrict__ att0, const float* __restrict__ att1,
                       const float* __restrict__ att2) {
    int i = blockIdx.x * SBLK + threadIdx.x;
    if (i < N3) g_cnt[i] = 0;
    if (i < 3 * 64) {
        int t = i >> 6, c = i & 63;
        const float* a = t == 0 ? att0 : (t == 1 ? att1 : att2);
        g_att[t][c] = c < DOUT ? a[c] : 0.f;
    }
}

// ---------------- histogram of destinations (real edges only) --------------
__global__ void k_hist(const int* __restrict__ ei0, const int* __restrict__ ei1,
                       const int* __restrict__ ei2) {
    int i = blockIdx.x * blockDim.x + threadIdx.x;
    if (i >= E3) return;
    int tag = i >= 2 * EE ? 2 : (i >= EE ? 1 : 0);
    const int* ei = tag == 0 ? ei0 : (tag == 1 ? ei1 : ei2);
    int l = i - tag * EE;
    int dst = __ldg(ei + EE + l);
    atomicAdd(&g_cnt[tag * NN + dst], 1);
}

// ---------------- scan: block sums -> exclusive partials -> offsets --------
__global__ void k_scanA() {
    __shared__ int red[SBLK];
    int i = blockIdx.x * SBLK + threadIdx.x;
    red[threadIdx.x] = i < N3 ? g_cnt[i] : 0;
    __syncthreads();
    for (int o = SBLK / 2; o; o >>= 1) {
        if (threadIdx.x < o) red[threadIdx.x] += red[threadIdx.x + o];
        __syncthreads();
    }
    if (threadIdx.x == 0) g_part[blockIdx.x] = red[0];
}

__global__ void k_scanB() {   // single block of 1024: exclusive scan of partials
    __shared__ int s[1024];
    int t = threadIdx.x;
    s[t] = t < NSB ? g_part[t] : 0;
    __syncthreads();
    for (int o = 1; o < 1024; o <<= 1) {
        int add = t >= o ? s[t - o] : 0;
        __syncthreads();
        s[t] += add;
        __syncthreads();
    }
    if (t < NSB) g_part[t] = t == 0 ? 0 : s[t - 1];
}

__global__ void k_scanC() {
    __shared__ int s[SBLK];
    int i = blockIdx.x * SBLK + threadIdx.x;
    int t = threadIdx.x;
    int v = i < N3 ? g_cnt[i] : 0;
    s[t] = v;
    __syncthreads();
    for (int o = 1; o < SBLK; o <<= 1) {
        int add = t >= o ? s[t - o] : 0;
        __syncthreads();
        s[t] += add;
        __syncthreads();
    }
    if (i < N3) {
        g_off[i] = g_part[blockIdx.x] + s[t] - v;  // exclusive
        g_cnt[i] = 0;                              // reset as scatter cursor
    }
}

// ---------------- scatter sources into dst-sorted order --------------------
__global__ void k_scatter(const int* __restrict__ ei0, const int* __restrict__ ei1,
                          const int* __restrict__ ei2) {
    int i = blockIdx.x * blockDim.x + threadIdx.x;
    if (i >= E3) return;
    int tag = i >= 2 * EE ? 2 : (i >= EE ? 1 : 0);
    const int* ei = tag == 0 ? ei0 : (tag == 1 ? ei1 : ei2);
    int l = i - tag * EE;
    int src = __ldg(ei + l);
    int dst = __ldg(ei + EE + l);
    int dg = tag * NN + dst;
    int slot = __ldg(&g_off[dg]) + atomicAdd(&g_cnt[dg], 1);
    g_srcs[slot] = src;
}

// ---------------- node transforms: xl/xr for all 3 tags --------------------
__global__ void k1(const float* __restrict__ x,
                   const float* __restrict__ Wl0, const float* __restrict__ bl0,
                   const float* __restrict__ Wr0, const float* __restrict__ br0,
                   const float* __restrict__ Wl1, const float* __restrict__ bl1,
                   const float* __restrict__ Wr1, const float* __restrict__ br1,
                   const float* __restrict__ Wl2, const float* __restrict__ bl2,
                   const float* __restrict__ Wr2, const float* __restrict__ br2) {
    __shared__ float sW[6][DIN * DOUT];
    __shared__ float sb[6][DOUT];
    {
        const float* Ws[6] = {Wl0, Wr0, Wl1, Wr1, Wl2, Wr2};
        const float* bs[6] = {bl0, br0, bl1, br1, bl2, br2};
        for (int w = 0; w < 6; w++) {
            for (int i = threadIdx.x; i < DIN * DOUT; i += blockDim.x) sW[w][i] = Ws[w][i];
            for (int i = threadIdx.x; i < DOUT; i += blockDim.x) sb[w][i] = bs[w][i];
        }
    }
    __syncthreads();
    int n = blockIdx.x * blockDim.x + threadIdx.x;
    if (n >= NN) return;

    float xv[DIN];
#pragma unroll
    for (int k = 0; k < DIN; k++) xv[k] = x[n * DIN + k];

    for (int w = 0; w < 6; w++) {
        int t = w >> 1;
        float* dst = ((w & 1) ? g_xr : g_xl) + (t * NN + n) * XS;
        const float* Wp = sW[w];
        const float* bp = sb[w];
        for (int j4 = 0; j4 < 48; j4 += 4) {
            float a0 = bp[j4], a1 = bp[j4 + 1], a2 = bp[j4 + 2], a3 = bp[j4 + 3];
#pragma unroll
            for (int k = 0; k < DIN; k++) {
                float xk = xv[k];
                const float* wr = &Wp[k * DOUT + j4];
                a0 += xk * wr[0]; a1 += xk * wr[1]; a2 += xk * wr[2]; a3 += xk * wr[3];
            }
            *reinterpret_cast<float4*>(dst + j4) = make_float4(a0, a1, a2, a3);
        }
        float a0 = bp[48], a1 = bp[49];
#pragma unroll
        for (int k = 0; k < DIN; k++) {
            float xk = xv[k];
            a0 += xk * Wp[k * DOUT + 48];
            a1 += xk * Wp[k * DOUT + 49];
        }
        *reinterpret_cast<float2*>(dst + 48) = make_float2(a0, a1);
    }
}

// ---------------- fold proj_W @ cls_W1 (no activation between) -------------
__global__ void k_fold(const float* __restrict__ P, const float* __restrict__ pb,
                       const float* __restrict__ W1, const float* __restrict__ b1) {
    int idx = blockIdx.x * blockDim.x + threadIdx.x;
    if (idx < 150 * 75) {
        int k = idx / 75, j = idx % 75;
        float a = 0.f;
        for (int m = 0; m < 150; m++) a += P[k * 150 + m] * W1[m * 75 + j];
        g_Wc[idx] = a;
    } else if (idx < 150 * 75 + 75) {
        int j = idx - 150 * 75;
        float a = b1[j];
        for (int m = 0; m < 150; m++) a += pb[m] * W1[m * 75 + j];
        g_bc[j] = a;
    }
}

// ---------------- CSR aggregation: 16-lane group per destination node ------
// xr[dst] + att loaded once per node; loop over sorted sources; register acc;
// single coalesced store. No atomics, no REDs, no zero-init of g_out.
__global__ void __launch_bounds__(256) k_agg() {
    int gid = (blockIdx.x * 256 + threadIdx.x) >> 4;   // destination row (= tag*NN + n)
    int c = threadIdx.x & 15;
    if (gid >= N3) return;
    int tag = gid >= 2 * NN ? 2 : (gid >= NN ? 1 : 0);

    bool act = c < 13;
    float4 xr4 = make_float4(0.f, 0.f, 0.f, 0.f);
    float4 at4 = xr4, v4 = xr4;
    int rb = gid * XS4;
    if (act) {
        xr4 = reinterpret_cast<const float4*>(g_xr)[rb + c];
        at4 = *reinterpret_cast<const float4*>(&g_att[tag][c * 4]);
        v4  = reinterpret_cast<const float4*>(g_xl)[rb + c];   // self loop: src = n
    }

    // self-loop seed
    float s, a;
    a = v4.x + xr4.x; a = a > 0.f ? a : 0.2f * a; s  = a * at4.x;
    a = v4.y + xr4.y; a = a > 0.f ? a : 0.2f * a; s += a * at4.y;
    a = v4.z + xr4.z; a = a > 0.f ? a : 0.2f * a; s += a * at4.z;
    a = v4.w + xr4.w; a = a > 0.f ? a : 0.2f * a; s += a * at4.w;
#pragma unroll
    for (int o = 8; o; o >>= 1) s += __shfl_xor_sync(0xffffffffu, s, o, 16);
    float e = __expf(s);
    float sum = e;
    float4 acc = make_float4(e * v4.x, e * v4.y, e * v4.z, e * v4.w);

    int e0 = g_off[gid];
    int e1 = gid == N3 - 1 ? E3 : g_off[gid + 1];
    int base = tag * NN * XS4;

    for (int p = e0; p < e1; p++) {
        int src = __ldg(&g_srcs[p]);                    // broadcast within group
        float4 w4 = make_float4(0.f, 0.f, 0.f, 0.f);
        if (act) w4 = reinterpret_cast<const float4*>(g_xl)[base + src * XS4 + c];
        a = w4.x + xr4.x; a = a > 0.f ? a : 0.2f * a; s  = a * at4.x;
        a = w4.y + xr4.y; a = a > 0.f ? a : 0.2f * a; s += a * at4.y;
        a = w4.z + xr4.z; a = a > 0.f ? a : 0.2f * a; s += a * at4.z;
        a = w4.w + xr4.w; a = a > 0.f ? a : 0.2f * a; s += a * at4.w;
#pragma unroll
        for (int o = 8; o; o >>= 1) s += __shfl_xor_sync(0xffffffffu, s, o, 16);
        e = __expf(s);
        sum += e;
        acc.x += e * w4.x; acc.y += e * w4.y; acc.z += e * w4.z; acc.w += e * w4.w;
    }

    if (act) reinterpret_cast<float4*>(g_out)[rb + c] = acc;
    if (c == 0) g_sum[gid] = sum;
}

// ---------------- fused head: normalize -> leaky -> folded MLP -------------
#define K4N 256
__global__ void __launch_bounds__(K4N) k4(
        const float* __restrict__ bo_p, const float* __restrict__ bo_s,
        const float* __restrict__ bo_v,
        const float* __restrict__ W2, const float* __restrict__ b2,
        const float* __restrict__ W3, const float* __restrict__ b3,
        float* __restrict__ out) {
    extern __shared__ float sm[];
    float* sWc  = sm;                 // 11250
    float* sbc  = sWc + 11250;        // 75
    float* sW2  = sbc + 75;           // 2250
    float* sb2  = sW2 + 2250;         // 30
    float* sW3  = sb2 + 30;           // 60
    float* sb3  = sW3 + 60;           // 2
    float* sinv = sb3 + 2;            // 3 * K4N
    float* tile = sinv + 3 * K4N;     // K4N * 151 (odd stride: conflict-free)

    int tid = threadIdx.x;
    int nb = blockIdx.x * K4N;
    for (int i = tid; i < 11250; i += K4N) sWc[i] = g_Wc[i];
    for (int i = tid; i < 2250;  i += K4N) sW2[i] = W2[i];
    if (tid < 75) sbc[tid] = g_bc[tid];
    if (tid < 30) sb2[tid] = b2[tid];
    if (tid < 60) sW3[tid] = W3[tid];
    if (tid < 2)  sb3[tid] = b3[tid];
    for (int i = tid; i < 3 * K4N; i += K4N) {
        int t = i / K4N, r = i % K4N;
        int n = nb + r;
        sinv[i] = n < NN ? 1.f / (g_sum[t * NN + n] + 1e-16f) : 0.f;
    }
    __syncthreads();

    const float* bos[3] = {bo_p, bo_s, bo_v};
    for (int t = 0; t < 3; t++) {
        const float* bo = bos[t];
        for (int idx = tid; idx < K4N * 50; idx += K4N) {
            int r = idx / 50, cc = idx % 50;
            int n = nb + r;
            float v = 0.f;
            if (n < NN)
                v = g_out[(t * NN + n) * XS + cc] * sinv[t * K4N + r] + __ldg(&bo[cc]);
            tile[r * 151 + t * 50 + cc] = v > 0.f ? v : 0.1f * v;
        }
    }
    __syncthreads();

    int n = nb + tid;
    if (n >= NN) return;

    float acc2[75];
#pragma unroll
    for (int j = 0; j < 75; j++) acc2[j] = sbc[j];
    const float* hrow = &tile[tid * 151];
    for (int k = 0; k < 150; k++) {
        float hk = hrow[k];
        const float* wr = &sWc[k * 75];
#pragma unroll
        for (int j = 0; j < 75; j++) acc2[j] += hk * wr[j];
    }
    float* h2 = &tile[tid * 151];
#pragma unroll
    for (int j = 0; j < 75; j++) { float v = acc2[j]; h2[j] = v > 0.f ? v : 0.1f * v; }

    float acc3[30];
#pragma unroll
    for (int j = 0; j < 30; j++) acc3[j] = sb2[j];
    for (int k = 0; k < 75; k++) {
        float hk = h2[k];
        const float* wr = &sW2[k * 30];
#pragma unroll
        for (int j = 0; j < 30; j++) acc3[j] += hk * wr[j];
    }

    float o0 = sb3[0], o1 = sb3[1];
#pragma unroll
    for (int k = 0; k < 30; k++) {
        float v = acc3[k];
        v = v > 0.f ? v : 0.1f * v;
        o0 += v * sW3[k * 2];
        o1 += v * sW3[k * 2 + 1];
    }
    out[n * 2]     = o0;
    out[n * 2 + 1] = o1;
}

// ---------------- launch -----------------------------------------------------
extern "C" void kernel_launch(void* const* d_in, const int* in_sizes, int n_in,
                              void* d_out, int out_size) {
    const float* x    = (const float*)d_in[0];
    const int*   eis[3] = {(const int*)d_in[1], (const int*)d_in[2], (const int*)d_in[3]};
    const float *Wl[3], *bl[3], *Wr[3], *br[3], *att[3], *bo[3];
    int i = 4;
    for (int t = 0; t < 3; t++) {
        Wl[t]  = (const float*)d_in[i++];
        bl[t]  = (const float*)d_in[i++];
        Wr[t]  = (const float*)d_in[i++];
        br[t]  = (const float*)d_in[i++];
        att[t] = (const float*)d_in[i++];
        bo[t]  = (const float*)d_in[i++];
    }
    const float* proj_W = (const float*)d_in[22];
    const float* proj_b = (const float*)d_in[23];
    const float* cls_W1 = (const float*)d_in[24];
    const float* cls_b1 = (const float*)d_in[25];
    const float* cls_W2 = (const float*)d_in[26];
    const float* cls_b2 = (const float*)d_in[27];
    const float* cls_W3 = (const float*)d_in[28];
    const float* cls_b3 = (const float*)d_in[29];
    float* out = (float*)d_out;

    const int SMEM_K4 = (11250 + 75 + 2250 + 30 + 60 + 2 + 3 * K4N + K4N * 151) * 4;
    cudaFuncSetAttribute(k4, cudaFuncAttributeMaxDynamicSharedMemorySize, SMEM_K4);

    k_init<<<NSB, SBLK>>>(att[0], att[1], att[2]);
    k_hist<<<(E3 + 255) / 256, 256>>>(eis[0], eis[1], eis[2]);
    k_scanA<<<NSB, SBLK>>>();
    k_scanB<<<1, 1024>>>();
    k_scanC<<<NSB, SBLK>>>();
    k_scatter<<<(E3 + 255) / 256, 256>>>(eis[0], eis[1], eis[2]);
    k1<<<(NN + 127) / 128, 128>>>(x,
                                  Wl[0], bl[0], Wr[0], br[0],
                                  Wl[1], bl[1], Wr[1], br[1],
                                  Wl[2], bl[2], Wr[2], br[2]);
    k_fold<<<(150 * 75 + 75 + 127) / 128, 128>>>(proj_W, proj_b, cls_W1, cls_b1);
    k_agg<<<(N3 * 16 + 255) / 256, 256>>>();
    k4<<<(NN + K4N - 1) / K4N, K4N, SMEM_K4>>>(bo[0], bo[1], bo[2],
                                               cls_W2, cls_b2, cls_W3, cls_b3, out);
}

// round 4
// speedup vs baseline: 2.2767x; 1.1672x over previous
#include <cuda_runtime.h>
#include <math.h>

#define NN   100000
#define N3   (3 * NN)
#define EE   1600000
#define E3   (3 * EE)
#define XS   64              // padded row stride (64*4 = 256B: rows = exactly 2 lines)
#define XS4  16              // row stride in float4
#define DIN  25
#define DOUT 50
#define SBLK 512
#define NSB  ((N3 + SBLK - 1) / SBLK)   // 586

// ---------------- f32x2 packed helpers ----------------
__device__ __forceinline__ unsigned long long pk2(float x) {
    unsigned long long r; asm("mov.b64 %0,{%1,%1};" : "=l"(r) : "f"(x)); return r;
}
__device__ __forceinline__ unsigned long long pkxy(float x, float y) {
    unsigned long long r; asm("mov.b64 %0,{%1,%2};" : "=l"(r) : "f"(x), "f"(y)); return r;
}
__device__ __forceinline__ void fma2(unsigned long long& d, unsigned long long a,
                                     unsigned long long b) {
    asm("fma.rn.f32x2 %0,%1,%2,%0;" : "+l"(d) : "l"(a), "l"(b));
}
__device__ __forceinline__ float2 up2(unsigned long long v) {
    float2 f; asm("mov.b64 {%0,%1},%2;" : "=f"(f.x), "=f"(f.y) : "l"(v)); return f;
}

// ---------------- scratch (device globals) ----------------
__device__ __align__(16) float g_xl[3 * NN * XS];   // pads never written -> stay 0
__device__ __align__(16) float g_xr[3 * NN * XS];
__device__ __align__(16) float g_out[3 * NN * XS];  // fully overwritten (cols 0..51)
__device__ float g_sum[N3];
__device__ float g_att[3][64];       // zero-padded attention vectors
__device__ float g_Wc[150 * 76];     // folded proj_W @ cls_W1, padded to 76 cols
__device__ float g_bc[76];
__device__ int   g_cnt[N3];          // histogram, then scatter cursor
__device__ int   g_off[N3];          // CSR offsets
__device__ int   g_srcs[E3];         // dst-sorted source ids
__device__ int   g_part[1024];       // scan partials

// ---------------- node transforms: xl/xr for all 3 tags (f32x2) -----------
__global__ void __launch_bounds__(128) k1(const float* __restrict__ x,
                   const float* __restrict__ Wl0, const float* __restrict__ bl0,
                   const float* __restrict__ Wr0, const float* __restrict__ br0,
                   const float* __restrict__ Wl1, const float* __restrict__ bl1,
                   const float* __restrict__ Wr1, const float* __restrict__ br1,
                   const float* __restrict__ Wl2, const float* __restrict__ bl2,
                   const float* __restrict__ Wr2, const float* __restrict__ br2) {
    __shared__ __align__(16) float sW[6][DIN * DOUT];
    __shared__ __align__(16) float sb[6][DOUT];
    __shared__ float sX[128 * DIN];
    {
        const float* Ws[6] = {Wl0, Wr0, Wl1, Wr1, Wl2, Wr2};
        const float* bs[6] = {bl0, br0, bl1, br1, bl2, br2};
        for (int w = 0; w < 6; w++) {
            for (int i = threadIdx.x; i < DIN * DOUT; i += 128) sW[w][i] = Ws[w][i];
            for (int i = threadIdx.x; i < DOUT; i += 128) sb[w][i] = bs[w][i];
        }
    }
    int nb = blockIdx.x * 128;
    for (int i = threadIdx.x; i < 128 * DIN; i += 128) {
        int g = nb * DIN + i;
        sX[i] = g < NN * DIN ? x[g] : 0.f;
    }
    __syncthreads();
    int n = nb + threadIdx.x;
    if (n >= NN) return;

    float xv[DIN];
#pragma unroll
    for (int k = 0; k < DIN; k++) xv[k] = sX[threadIdx.x * DIN + k];
    unsigned long long xp[DIN];
#pragma unroll
    for (int k = 0; k < DIN; k++) xp[k] = pk2(xv[k]);

    for (int w = 0; w < 6; w++) {
        int t = w >> 1;
        float* dst = ((w & 1) ? g_xr : g_xl) + (t * NN + n) * XS;
        const unsigned long long* Wp = reinterpret_cast<const unsigned long long*>(sW[w]);
        const float* bp = sb[w];
        unsigned long long acc[25];
#pragma unroll
        for (int j = 0; j < 25; j++) acc[j] = pkxy(bp[2 * j], bp[2 * j + 1]);
#pragma unroll
        for (int k = 0; k < DIN; k++) {
            const unsigned long long* wr = &Wp[k * 25];
#pragma unroll
            for (int j = 0; j < 25; j++) fma2(acc[j], xp[k], wr[j]);
        }
#pragma unroll
        for (int j = 0; j < 25; j++)
            *reinterpret_cast<unsigned long long*>(dst + 2 * j) = acc[j];
    }
}

// ---------------- fold proj_W @ cls_W1 (padded to 76 cols) -----------------
__global__ void k_fold(const float* __restrict__ P, const float* __restrict__ pb,
                       const float* __restrict__ W1, const float* __restrict__ b1) {
    int idx = blockIdx.x * blockDim.x + threadIdx.x;
    if (idx < 150 * 76) {
        int k = idx / 76, j = idx % 76;
        float a = 0.f;
        if (j < 75) for (int m = 0; m < 150; m++) a += P[k * 150 + m] * W1[m * 75 + j];
        g_Wc[idx] = a;
    } else if (idx < 150 * 76 + 76) {
        int j = idx - 150 * 76;
        float a = 0.f;
        if (j < 75) { a = b1[j]; for (int m = 0; m < 150; m++) a += pb[m] * W1[m * 75 + j]; }
        g_bc[j] = a;
    }
}

// ---------------- init: zero histogram + stage padded att ------------------
__global__ void k_init(const float* __restrict__ att0, const float* __restrict__ att1,
                       const float* __restrict__ att2) {
    int i = blockIdx.x * SBLK + threadIdx.x;
    if (i < N3) g_cnt[i] = 0;
    if (i < 3 * 64) {
        int t = i >> 6, c = i & 63;
        const float* a = t == 0 ? att0 : (t == 1 ? att1 : att2);
        g_att[t][c] = c < DOUT ? a[c] : 0.f;
    }
}

// ---------------- histogram of destinations --------------------------------
__global__ void k_hist(const int* __restrict__ ei0, const int* __restrict__ ei1,
                       const int* __restrict__ ei2) {
    int i = blockIdx.x * blockDim.x + threadIdx.x;
    if (i >= E3) return;
    int tag = i >= 2 * EE ? 2 : (i >= EE ? 1 : 0);
    const int* ei = tag == 0 ? ei0 : (tag == 1 ? ei1 : ei2);
    int l = i - tag * EE;
    int dst = __ldg(ei + EE + l);
    atomicAdd(&g_cnt[tag * NN + dst], 1);
}

// ---------------- scan passes ----------------------------------------------
__global__ void k_scanA() {
    __shared__ int red[SBLK];
    int i = blockIdx.x * SBLK + threadIdx.x;
    red[threadIdx.x] = i < N3 ? g_cnt[i] : 0;
    __syncthreads();
    for (int o = SBLK / 2; o; o >>= 1) {
        if (threadIdx.x < o) red[threadIdx.x] += red[threadIdx.x + o];
        __syncthreads();
    }
    if (threadIdx.x == 0) g_part[blockIdx.x] = red[0];
}

__global__ void k_scanB() {
    __shared__ int s[1024];
    int t = threadIdx.x;
    s[t] = t < NSB ? g_part[t] : 0;
    __syncthreads();
    for (int o = 1; o < 1024; o <<= 1) {
        int add = t >= o ? s[t - o] : 0;
        __syncthreads();
        s[t] += add;
        __syncthreads();
    }
    if (t < NSB) g_part[t] = t == 0 ? 0 : s[t - 1];
}

__global__ void k_scanC() {
    __shared__ int s[SBLK];
    int i = blockIdx.x * SBLK + threadIdx.x;
    int t = threadIdx.x;
    int v = i < N3 ? g_cnt[i] : 0;
    s[t] = v;
    __syncthreads();
    for (int o = 1; o < SBLK; o <<= 1) {
        int add = t >= o ? s[t - o] : 0;
        __syncthreads();
        s[t] += add;
        __syncthreads();
    }
    if (i < N3) {
        g_off[i] = g_part[blockIdx.x] + s[t] - v;
        g_cnt[i] = 0;
    }
}

// ---------------- scatter sources into dst-sorted order --------------------
__global__ void k_scatter(const int* __restrict__ ei0, const int* __restrict__ ei1,
                          const int* __restrict__ ei2) {
    int i = blockIdx.x * blockDim.x + threadIdx.x;
    if (i >= E3) return;
    int tag = i >= 2 * EE ? 2 : (i >= EE ? 1 : 0);
    const int* ei = tag == 0 ? ei0 : (tag == 1 ? ei1 : ei2);
    int l = i - tag * EE;
    int src = __ldg(ei + l);
    int dst = __ldg(ei + EE + l);
    int dg = tag * NN + dst;
    int slot = __ldg(&g_off[dg]) + atomicAdd(&g_cnt[dg], 1);
    g_srcs[slot] = src;
}

// ---------------- CSR aggregation: warp per node, 2 edges/iteration --------
__global__ void __launch_bounds__(256) k_agg() {
    int gid = (blockIdx.x * 256 + threadIdx.x) >> 5;   // destination row (tag*NN + n)
    if (gid >= N3) return;
    int lane = threadIdx.x & 31;
    int c = lane & 15, half = lane >> 4;
    int tag = gid >= 2 * NN ? 2 : (gid >= NN ? 1 : 0);
    bool act = c < 13;

    float4 xr4 = make_float4(0.f, 0.f, 0.f, 0.f), at4 = xr4;
    int rb = gid * XS4;
    if (act) {
        xr4 = reinterpret_cast<const float4*>(g_xr)[rb + c];
        at4 = *reinterpret_cast<const float4*>(&g_att[tag][c * 4]);
    }

    int e0 = g_off[gid];
    int e1 = gid == N3 - 1 ? E3 : g_off[gid + 1];
    int deg = e1 - e0 + 1;              // +1: self loop at virtual index 0
    int nloc = gid - tag * NN;
    const float4* xlb = reinterpret_cast<const float4*>(g_xl) + tag * NN * XS4;

    float sum = 0.f;
    float4 acc = make_float4(0.f, 0.f, 0.f, 0.f);

    for (int base = 0; base < deg; base += 32) {
        int idx = base + lane;
        int sv = 0;
        if (idx < deg) sv = idx == 0 ? nloc : __ldg(&g_srcs[e0 + idx - 1]);
        int m = min(32, deg - base);
        for (int i = 0; i < m; i += 2) {
            int s = __shfl_sync(0xffffffffu, sv, i + half);   // half0: edge i, half1: i+1
            bool ev = (i + half) < m;
            float4 w4 = make_float4(0.f, 0.f, 0.f, 0.f);
            if (act) w4 = xlb[s * XS4 + c];
            float a, sc;
            a = w4.x + xr4.x; a = a > 0.f ? a : 0.2f * a; sc  = a * at4.x;
            a = w4.y + xr4.y; a = a > 0.f ? a : 0.2f * a; sc += a * at4.y;
            a = w4.z + xr4.z; a = a > 0.f ? a : 0.2f * a; sc += a * at4.z;
            a = w4.w + xr4.w; a = a > 0.f ? a : 0.2f * a; sc += a * at4.w;
#pragma unroll
            for (int o = 8; o; o >>= 1) sc += __shfl_xor_sync(0xffffffffu, sc, o, 16);
            float e = ev ? __expf(sc) : 0.f;
            sum += e;
            acc.x += e * w4.x; acc.y += e * w4.y;
            acc.z += e * w4.z; acc.w += e * w4.w;
        }
    }
    // combine the two halves
    acc.x += __shfl_xor_sync(0xffffffffu, acc.x, 16);
    acc.y += __shfl_xor_sync(0xffffffffu, acc.y, 16);
    acc.z += __shfl_xor_sync(0xffffffffu, acc.z, 16);
    acc.w += __shfl_xor_sync(0xffffffffu, acc.w, 16);
    sum   += __shfl_xor_sync(0xffffffffu, sum, 16);

    if (half == 0 && act) reinterpret_cast<float4*>(g_out)[rb + c] = acc;
    if (lane == 0) g_sum[gid] = sum;
}

// ---------------- fused head: normalize -> leaky -> folded MLP (f32x2) -----
#define K4N 256
__global__ void __launch_bounds__(K4N) k4(
        const float* __restrict__ bo_p, const float* __restrict__ bo_s,
        const float* __restrict__ bo_v,
        const float* __restrict__ W2, const float* __restrict__ b2,
        const float* __restrict__ W3, const float* __restrict__ b3,
        float* __restrict__ out) {
    extern __shared__ __align__(16) float sm[];
    float* sWc  = sm;                 // 11400 (150 x 76, rows 16B-aligned)
    float* sbc  = sWc + 11400;        // 76
    float* sW2  = sbc + 76;           // 2250
    float* sb2  = sW2 + 2250;         // 30
    float* sW3  = sb2 + 30;           // 60
    float* sb3  = sW3 + 60;           // 2
    float* sinv = sb3 + 2;            // 3 * K4N
    float* tile = sinv + 3 * K4N;     // K4N * 151

    int tid = threadIdx.x;
    int nb = blockIdx.x * K4N;
    for (int i = tid; i < 11400; i += K4N) sWc[i] = g_Wc[i];
    for (int i = tid; i < 2250;  i += K4N) sW2[i] = W2[i];
    if (tid < 76) sbc[tid] = g_bc[tid];
    if (tid < 30) sb2[tid] = b2[tid];
    if (tid < 60) sW3[tid] = W3[tid];
    if (tid < 2)  sb3[tid] = b3[tid];
    for (int i = tid; i < 3 * K4N; i += K4N) {
        int t = i / K4N, r = i % K4N;
        int n = nb + r;
        sinv[i] = n < NN ? 1.f / (g_sum[t * NN + n] + 1e-16f) : 0.f;
    }
    __syncthreads();

    const float* bos[3] = {bo_p, bo_s, bo_v};
    for (int t = 0; t < 3; t++) {
        const float* bo = bos[t];
        for (int idx = tid; idx < K4N * 50; idx += K4N) {
            int r = idx / 50, cc = idx % 50;
            int n = nb + r;
            float v = 0.f;
            if (n < NN)
                v = g_out[(t * NN + n) * XS + cc] * sinv[t * K4N + r] + __ldg(&bo[cc]);
            tile[r * 151 + t * 50 + cc] = v > 0.f ? v : 0.1f * v;
        }
    }
    __syncthreads();

    int n = nb + tid;
    if (n >= NN) return;

    // layer 1: 150 -> 75 (packed, weights padded to 76)
    unsigned long long acc[38];
    const unsigned long long* bc64 = reinterpret_cast<const unsigned long long*>(sbc);
#pragma unroll
    for (int j = 0; j < 38; j++) acc[j] = bc64[j];
    const float* hrow = &tile[tid * 151];
    for (int k = 0; k < 150; k++) {
        unsigned long long hk2 = pk2(hrow[k]);
        const ulonglong2* wr = reinterpret_cast<const ulonglong2*>(&sWc[k * 76]);
#pragma unroll
        for (int j = 0; j < 19; j++) {
            ulonglong2 w2 = wr[j];
            fma2(acc[2 * j],     hk2, w2.x);
            fma2(acc[2 * j + 1], hk2, w2.y);
        }
    }
    float* h2 = &tile[tid * 151];
#pragma unroll
    for (int j = 0; j < 37; j++) {
        float2 f = up2(acc[j]);
        h2[2 * j]     = f.x > 0.f ? f.x : 0.1f * f.x;
        h2[2 * j + 1] = f.y > 0.f ? f.y : 0.1f * f.y;
    }
    { float2 f = up2(acc[37]); h2[74] = f.x > 0.f ? f.x : 0.1f * f.x; }

    // layer 2: 75 -> 30 (packed)
    unsigned long long acc3[15];
    const unsigned long long* b2p = reinterpret_cast<const unsigned long long*>(sb2);
#pragma unroll
    for (int j = 0; j < 15; j++) acc3[j] = b2p[j];
    for (int k = 0; k < 75; k++) {
        unsigned long long hk2 = pk2(h2[k]);
        const unsigned long long* wr = reinterpret_cast<const unsigned long long*>(&sW2[k * 30]);
#pragma unroll
        for (int j = 0; j < 15; j++) fma2(acc3[j], hk2, wr[j]);
    }

    // layer 3: 30 -> 2
    float o0 = sb3[0], o1 = sb3[1];
#pragma unroll
    for (int j = 0; j < 15; j++) {
        float2 f = up2(acc3[j]);
        float v = f.x > 0.f ? f.x : 0.1f * f.x;
        o0 += v * sW3[(2 * j) * 2];
        o1 += v * sW3[(2 * j) * 2 + 1];
        v = f.y > 0.f ? f.y : 0.1f * f.y;
        o0 += v * sW3[(2 * j + 1) * 2];
        o1 += v * sW3[(2 * j + 1) * 2 + 1];
    }
    out[n * 2]     = o0;
    out[n * 2 + 1] = o1;
}

// ---------------- launch -----------------------------------------------------
extern "C" void kernel_launch(void* const* d_in, const int* in_sizes, int n_in,
                              void* d_out, int out_size) {
    const float* x    = (const float*)d_in[0];
    const int*   eis[3] = {(const int*)d_in[1], (const int*)d_in[2], (const int*)d_in[3]};
    const float *Wl[3], *bl[3], *Wr[3], *br[3], *att[3], *bo[3];
    int i = 4;
    for (int t = 0; t < 3; t++) {
        Wl[t]  = (const float*)d_in[i++];
        bl[t]  = (const float*)d_in[i++];
        Wr[t]  = (const float*)d_in[i++];
        br[t]  = (const float*)d_in[i++];
        att[t] = (const float*)d_in[i++];
        bo[t]  = (const float*)d_in[i++];
    }
    const float* proj_W = (const float*)d_in[22];
    const float* proj_b = (const float*)d_in[23];
    const float* cls_W1 = (const float*)d_in[24];
    const float* cls_b1 = (const float*)d_in[25];
    const float* cls_W2 = (const float*)d_in[26];
    const float* cls_b2 = (const float*)d_in[27];
    const float* cls_W3 = (const float*)d_in[28];
    const float* cls_b3 = (const float*)d_in[29];
    float* out = (float*)d_out;

    const int SMEM_K4 = (11400 + 76 + 2250 + 30 + 60 + 2 + 3 * K4N + K4N * 151) * 4;
    cudaFuncSetAttribute(k4, cudaFuncAttributeMaxDynamicSharedMemorySize, SMEM_K4);

    // launch index 3 = k_hist (the slot ncu profiles)
    k1<<<(NN + 127) / 128, 128>>>(x,
                                  Wl[0], bl[0], Wr[0], br[0],
                                  Wl[1], bl[1], Wr[1], br[1],
                                  Wl[2], bl[2], Wr[2], br[2]);          // 0
    k_fold<<<(150 * 76 + 76 + 127) / 128, 128>>>(proj_W, proj_b, cls_W1, cls_b1); // 1
    k_init<<<NSB, SBLK>>>(att[0], att[1], att[2]);                      // 2
    k_hist<<<(E3 + 255) / 256, 256>>>(eis[0], eis[1], eis[2]);          // 3 <- profiled
    k_scanA<<<NSB, SBLK>>>();                                           // 4
    k_scanB<<<1, 1024>>>();                                             // 5
    k_scanC<<<NSB, SBLK>>>();                                           // 6
    k_scatter<<<(E3 + 255) / 256, 256>>>(eis[0], eis[1], eis[2]);       // 7
    k_agg<<<(N3 * 32 + 255) / 256, 256>>>();                            // 8
    k4<<<(NN + K4N - 1) / K4N, K4N, SMEM_K4>>>(bo[0], bo[1], bo[2],
                                               cls_W2, cls_b2, cls_W3, cls_b3, out); // 9
}

// round 6
// speedup vs baseline: 2.6743x; 1.1746x over previous
#include <cuda_runtime.h>
#include <math.h>

#define NN   100000
#define N3   (3 * NN)
#define EE   1600000
#define E3   (3 * EE)
#define XS   64              // padded row stride (256B rows = exactly 2 lines)
#define XS4  16
#define DIN  25
#define DOUT 50
#define SBLK 512
#define NSB  ((N3 + SBLK - 1) / SBLK)   // 586
#define HB   (E3 / 256)                 // 18750 (exact)

typedef unsigned long long ull;

// ---------------- f32x2 packed helpers ----------------
__device__ __forceinline__ ull pk2(float x) {
    ull r; asm("mov.b64 %0,{%1,%1};" : "=l"(r) : "f"(x)); return r;
}
__device__ __forceinline__ void fma2(ull& d, ull a, ull b) {
    asm("fma.rn.f32x2 %0,%1,%2,%0;" : "+l"(d) : "l"(a), "l"(b));
}
__device__ __forceinline__ float2 up2(ull v) {
    float2 f; asm("mov.b64 {%0,%1},%2;" : "=f"(f.x), "=f"(f.y) : "l"(v)); return f;
}

// ---------------- scratch ----------------
__device__ __align__(16) float g_xl[3 * NN * XS];   // pads never written -> stay 0
__device__ __align__(16) float g_xr[3 * NN * XS];
__device__ __align__(16) float g_out[3 * NN * XS];  // k_agg overwrites all 16 chunks
__device__ float g_sum[N3];
__device__ float g_att[3][64];
__device__ float g_Wc[150 * 76];
__device__ float g_bc[76];
__device__ int   g_cnt[N3];          // zeroed by k_agg tail for next replay
__device__ int   g_off[N3];          // exclusive offsets; consumed by scatter
__device__ int   g_srcs[E3];
__device__ int   g_part[1024];

// ---------------- L0: histogram + att staging ------------------------------
__global__ void k_pre(const int* __restrict__ ei0, const int* __restrict__ ei1,
                      const int* __restrict__ ei2,
                      const float* __restrict__ att0, const float* __restrict__ att1,
                      const float* __restrict__ att2) {
    int b = blockIdx.x;
    if (b < HB) {
        int i = b * 256 + threadIdx.x;
        int tag = i >= 2 * EE ? 2 : (i >= EE ? 1 : 0);
        const int* ei = tag == 0 ? ei0 : (tag == 1 ? ei1 : ei2);
        int l = i - tag * EE;
        int dst = __ldg(ei + EE + l);
        atomicAdd(&g_cnt[tag * NN + dst], 1);
    } else if (threadIdx.x < 192) {
        int t = threadIdx.x >> 6, c = threadIdx.x & 63;
        const float* a = t == 0 ? att0 : (t == 1 ? att1 : att2);
        g_att[t][c] = c < DOUT ? a[c] : 0.f;
    }
}

// ---------------- L1: per-block sums ----------------------------------------
__global__ void k_scanA() {
    __shared__ int red[SBLK];
    int i = blockIdx.x * SBLK + threadIdx.x;
    red[threadIdx.x] = i < N3 ? g_cnt[i] : 0;
    __syncthreads();
    for (int o = SBLK / 2; o; o >>= 1) {
        if (threadIdx.x < o) red[threadIdx.x] += red[threadIdx.x + o];
        __syncthreads();
    }
    if (threadIdx.x == 0) g_part[blockIdx.x] = red[0];
}

// ---------------- L2: block prefix (own reduction of partials) + local scan -
__global__ void k_scanBC() {
    __shared__ int s[SBLK];
    __shared__ int pref;
    int b = blockIdx.x, t = threadIdx.x;
    int p = 0;
    for (int i = t; i < b; i += SBLK) p += g_part[i];
    s[t] = p;
    __syncthreads();
    for (int o = SBLK / 2; o; o >>= 1) {
        if (t < o) s[t] += s[t + o];
        __syncthreads();
    }
    if (t == 0) pref = s[0];
    __syncthreads();
    int i = b * SBLK + t;
    int v = i < N3 ? g_cnt[i] : 0;
    s[t] = v;
    __syncthreads();
    for (int o = 1; o < SBLK; o <<= 1) {
        int add = t >= o ? s[t - o] : 0;
        __syncthreads();
        s[t] += add;
        __syncthreads();
    }
    if (i < N3) g_off[i] = pref + s[t] - v;   // exclusive
}

// ---------------- L3: scatter (consumes g_off) + weight fold ----------------
__global__ void k_scatter(const int* __restrict__ ei0, const int* __restrict__ ei1,
                          const int* __restrict__ ei2,
                          const float* __restrict__ P, const float* __restrict__ pb,
                          const float* __restrict__ W1, const float* __restrict__ b1) {
    int b = blockIdx.x;
    if (b < HB) {
        int i = b * 256 + threadIdx.x;
        int tag = i >= 2 * EE ? 2 : (i >= EE ? 1 : 0);
        const int* ei = tag == 0 ? ei0 : (tag == 1 ? ei1 : ei2);
        int l = i - tag * EE;
        int src = __ldg(ei + l);
        int dst = __ldg(ei + EE + l);
        int slot = atomicAdd(&g_off[tag * NN + dst], 1);
        g_srcs[slot] = src;
    } else {
        int idx = (b - HB) * 256 + threadIdx.x;
        if (idx < 150 * 76) {
            int k = idx / 76, j = idx % 76;
            float a = 0.f;
            if (j < 75) for (int m = 0; m < 150; m++) a += P[k * 150 + m] * W1[m * 75 + j];
            g_Wc[idx] = a;
        } else if (idx < 150 * 76 + 76) {
            int j = idx - 150 * 76;
            float a = 0.f;
            if (j < 75) { a = b1[j]; for (int m = 0; m < 150; m++) a += pb[m] * W1[m * 75 + j]; }
            g_bc[j] = a;
        }
    }
}

// ---------------- L4: node transforms (f32x2) -------------------------------
__global__ void __launch_bounds__(128) k1(const float* __restrict__ x,
                   const float* __restrict__ Wl0, const float* __restrict__ bl0,
                   const float* __restrict__ Wr0, const float* __restrict__ br0,
                   const float* __restrict__ Wl1, const float* __restrict__ bl1,
                   const float* __restrict__ Wr1, const float* __restrict__ br1,
                   const float* __restrict__ Wl2, const float* __restrict__ bl2,
                   const float* __restrict__ Wr2, const float* __restrict__ br2) {
    __shared__ __align__(16) float sW[6][DIN * DOUT];
    __shared__ __align__(16) float sb[6][DOUT];
    __shared__ float sX[128 * DIN];
    {
        const float* Ws[6] = {Wl0, Wr0, Wl1, Wr1, Wl2, Wr2};
        const float* bs[6] = {bl0, br0, bl1, br1, bl2, br2};
        for (int w = 0; w < 6; w++) {
            for (int i = threadIdx.x; i < DIN * DOUT; i += 128) sW[w][i] = Ws[w][i];
            for (int i = threadIdx.x; i < DOUT; i += 128) sb[w][i] = bs[w][i];
        }
    }
    int nb = blockIdx.x * 128;
    for (int i = threadIdx.x; i < 128 * DIN; i += 128) {
        int g = nb * DIN + i;
        sX[i] = g < NN * DIN ? x[g] : 0.f;
    }
    __syncthreads();
    int n = nb + threadIdx.x;
    if (n >= NN) return;

    ull xp[DIN];
#pragma unroll
    for (int k = 0; k < DIN; k++) xp[k] = pk2(sX[threadIdx.x * DIN + k]);

    for (int w = 0; w < 6; w++) {
        int t = w >> 1;
        float* dst = ((w & 1) ? g_xr : g_xl) + (t * NN + n) * XS;
        const ull* Wp = reinterpret_cast<const ull*>(sW[w]);
        const ull* bp = reinterpret_cast<const ull*>(sb[w]);
        ull acc[25];
#pragma unroll
        for (int j = 0; j < 25; j++) acc[j] = bp[j];
#pragma unroll
        for (int k = 0; k < DIN; k++) {
            const ull* wr = &Wp[k * 25];
#pragma unroll
            for (int j = 0; j < 25; j++) fma2(acc[j], xp[k], wr[j]);
        }
#pragma unroll
        for (int j = 0; j < 25; j++)
            *reinterpret_cast<ull*>(dst + 2 * j) = acc[j];
    }
}

// ---------------- L5: CSR aggregation: warp/node, 4-lane groups, 8 edges/it -
__global__ void __launch_bounds__(256) k_agg() {
    int gid = (blockIdx.x * 256 + threadIdx.x) >> 5;
    if (gid >= N3) return;
    int lane = threadIdx.x & 31;
    int g = lane >> 2, l = lane & 3;
    int tag = gid >= 2 * NN ? 2 : (gid >= NN ? 1 : 0);
    int nloc = gid - tag * NN;

    const float4* xlb = reinterpret_cast<const float4*>(g_xl) + tag * NN * XS4;
    const float4* xrr = reinterpret_cast<const float4*>(g_xr) + gid * XS4;

    float4 xr4[4], at4[4];
#pragma unroll
    for (int j = 0; j < 4; j++) {
        xr4[j] = __ldg(xrr + l + 4 * j);
        at4[j] = *reinterpret_cast<const float4*>(&g_att[tag][(l + 4 * j) * 4]);
    }

    int e1 = __ldg(&g_off[gid]);                        // inclusive end (post-scatter)
    int e0 = gid ? __ldg(&g_off[gid - 1]) : 0;
    int deg = e1 - e0 + 1;                              // + self loop (virtual idx 0)

    float sum = 0.f;
    float4 acc[4];
#pragma unroll
    for (int j = 0; j < 4; j++) acc[j] = make_float4(0.f, 0.f, 0.f, 0.f);

    for (int base = 0; base < deg; base += 32) {
        int idx = base + lane;
        int sv = 0;
        if (idx < deg) sv = idx == 0 ? nloc : __ldg(&g_srcs[e0 + idx - 1]);
        int m = min(32, deg - base);
        for (int i = 0; i < m; i += 8) {
            int eidx = i + g;
            int s = __shfl_sync(0xffffffffu, sv, eidx);
            bool ev = eidx < m;
            float4 w4[4];
            const float4* row = xlb + s * XS4;
#pragma unroll
            for (int j = 0; j < 4; j++) w4[j] = __ldg(row + l + 4 * j);
            float sc = 0.f;
#pragma unroll
            for (int j = 0; j < 4; j++) {
                float a;
                a = w4[j].x + xr4[j].x; a = a > 0.f ? a : 0.2f * a; sc += a * at4[j].x;
                a = w4[j].y + xr4[j].y; a = a > 0.f ? a : 0.2f * a; sc += a * at4[j].y;
                a = w4[j].z + xr4[j].z; a = a > 0.f ? a : 0.2f * a; sc += a * at4[j].z;
                a = w4[j].w + xr4[j].w; a = a > 0.f ? a : 0.2f * a; sc += a * at4[j].w;
            }
            sc += __shfl_xor_sync(0xffffffffu, sc, 1);
            sc += __shfl_xor_sync(0xffffffffu, sc, 2);
            float e = ev ? __expf(sc) : 0.f;
            sum += e;
#pragma unroll
            for (int j = 0; j < 4; j++) {
                acc[j].x += e * w4[j].x; acc[j].y += e * w4[j].y;
                acc[j].z += e * w4[j].z; acc[j].w += e * w4[j].w;
            }
        }
    }
    // combine the 8 edge-groups (xor over g bits only; each edge counted once)
#pragma unroll
    for (int o = 4; o <= 16; o <<= 1) {
#pragma unroll
        for (int j = 0; j < 4; j++) {
            acc[j].x += __shfl_xor_sync(0xffffffffu, acc[j].x, o);
            acc[j].y += __shfl_xor_sync(0xffffffffu, acc[j].y, o);
            acc[j].z += __shfl_xor_sync(0xffffffffu, acc[j].z, o);
            acc[j].w += __shfl_xor_sync(0xffffffffu, acc[j].w, o);
        }
        sum += __shfl_xor_sync(0xffffffffu, sum, o);
    }
    if (lane < 4) {
        float4* orow = reinterpret_cast<float4*>(g_out) + gid * XS4;
#pragma unroll
        for (int j = 0; j < 4; j++) orow[lane + 4 * j] = acc[j];
    }
    if (lane == 0) g_sum[gid] = sum;          // butterfly counted each edge once
    if (lane == 1) g_cnt[gid] = 0;            // reset histogram for next replay
}

// ---------------- L6: head, tile-free streaming (f32x2) ---------------------
#define K4N 128
__global__ void __launch_bounds__(K4N) k4(
        const float* __restrict__ bo_p, const float* __restrict__ bo_s,
        const float* __restrict__ bo_v,
        const float* __restrict__ W2, const float* __restrict__ b2,
        const float* __restrict__ W3, const float* __restrict__ b3,
        float* __restrict__ out) {
    extern __shared__ __align__(16) float sm4[];
    float* sWc = sm4;               // 11400 (150 x 76)
    float* sbc = sWc + 11400;       // 76
    float* sW2 = sbc + 76;          // 2250
    float* sb2 = sW2 + 2250;        // 30
    float* sW3 = sb2 + 30;          // 60
    float* sb3 = sW3 + 60;          // 2
    float* sbo = sb3 + 2;           // 150

    int tid = threadIdx.x;
    for (int i = tid; i < 11400; i += K4N) sWc[i] = g_Wc[i];
    for (int i = tid; i < 2250;  i += K4N) sW2[i] = W2[i];
    if (tid < 76) sbc[tid] = g_bc[tid];
    if (tid < 30) sb2[tid] = b2[tid];
    if (tid < 60) sW3[tid] = W3[tid];
    if (tid < 2)  sb3[tid] = b3[tid];
    if (tid < 50) {
        sbo[tid]       = bo_p[tid];
        sbo[50 + tid]  = bo_s[tid];
        sbo[100 + tid] = bo_v[tid];
    }
    __syncthreads();

    int n = blockIdx.x * K4N + tid;
    int nc = n < NN ? n : NN - 1;

    // layer 1: stream h from g_out (own row), acc in registers
    ull acc[38];
    const ull* bc64 = reinterpret_cast<const ull*>(sbc);
#pragma unroll
    for (int j = 0; j < 38; j++) acc[j] = bc64[j];

    for (int t = 0; t < 3; t++) {
        float invt = 1.f / (g_sum[t * NN + nc] + 1e-16f);
        const float4* grow = reinterpret_cast<const float4*>(g_out) + (t * NN + nc) * XS4;
        const float* bot = &sbo[t * 50];
        const float* wbase = &sWc[t * 50 * 76];
        for (int q = 0; q < 12; q++) {
            float4 hv = __ldg(grow + q);
            float hc[4] = {hv.x, hv.y, hv.z, hv.w};
#pragma unroll
            for (int c = 0; c < 4; c++) {
                float v = hc[c] * invt + bot[q * 4 + c];
                v = v > 0.f ? v : 0.1f * v;
                ull h2 = pk2(v);
                const ulonglong2* wr =
                    reinterpret_cast<const ulonglong2*>(wbase + (q * 4 + c) * 76);
#pragma unroll
                for (int j = 0; j < 19; j++) {
                    ulonglong2 w2 = wr[j];
                    fma2(acc[2 * j], h2, w2.x);
                    fma2(acc[2 * j + 1], h2, w2.y);
                }
            }
        }
        // chunk 12: cols 48,49 only
        float4 hv = __ldg(grow + 12);
        float hc[2] = {hv.x, hv.y};
#pragma unroll
        for (int c = 0; c < 2; c++) {
            float v = hc[c] * invt + bot[48 + c];
            v = v > 0.f ? v : 0.1f * v;
            ull h2 = pk2(v);
            const ulonglong2* wr =
                reinterpret_cast<const ulonglong2*>(wbase + (48 + c) * 76);
#pragma unroll
            for (int j = 0; j < 19; j++) {
                ulonglong2 w2 = wr[j];
                fma2(acc[2 * j], h2, w2.x);
                fma2(acc[2 * j + 1], h2, w2.y);
            }
        }
    }

    // layer 2: 75 -> 30, h2 comes straight from acc registers
    ull acc3[15];
    const ull* b2p = reinterpret_cast<const ull*>(sb2);
#pragma unroll
    for (int j = 0; j < 15; j++) acc3[j] = b2p[j];
#pragma unroll
    for (int kp = 0; kp < 38; kp++) {
        float2 f = up2(acc[kp]);
        {
            float v = f.x > 0.f ? f.x : 0.1f * f.x;
            ull h2 = pk2(v);
            const ull* wr = reinterpret_cast<const ull*>(&sW2[(2 * kp) * 30]);
#pragma unroll
            for (int j = 0; j < 15; j++) fma2(acc3[j], h2, wr[j]);
        }
        if (kp < 37) {
            float v = f.y > 0.f ? f.y : 0.1f * f.y;
            ull h2 = pk2(v);
            const ull* wr = reinterpret_cast<const ull*>(&sW2[(2 * kp + 1) * 30]);
#pragma unroll
            for (int j = 0; j < 15; j++) fma2(acc3[j], h2, wr[j]);
        }
    }

    // layer 3: 30 -> 2
    float o0 = sb3[0], o1 = sb3[1];
#pragma unroll
    for (int j = 0; j < 15; j++) {
        float2 f = up2(acc3[j]);
        float v = f.x > 0.f ? f.x : 0.1f * f.x;
        o0 += v * sW3[(2 * j) * 2];
        o1 += v * sW3[(2 * j) * 2 + 1];
        v = f.y > 0.f ? f.y : 0.1f * f.y;
        o0 += v * sW3[(2 * j + 1) * 2];
        o1 += v * sW3[(2 * j + 1) * 2 + 1];
    }
    if (n < NN) *reinterpret_cast<float2*>(&out[n * 2]) = make_float2(o0, o1);
}

// ---------------- launch -----------------------------------------------------
extern "C" void kernel_launch(void* const* d_in, const int* in_sizes, int n_in,
                              void* d_out, int out_size) {
    const float* x    = (const float*)d_in[0];
    const int*   eis[3] = {(const int*)d_in[1], (const int*)d_in[2], (const int*)d_in[3]};
    const float *Wl[3], *bl[3], *Wr[3], *br[3], *att[3], *bo[3];
    int i = 4;
    for (int t = 0; t < 3; t++) {
        Wl[t]  = (const float*)d_in[i++];
        bl[t]  = (const float*)d_in[i++];
        Wr[t]  = (const float*)d_in[i++];
        br[t]  = (const float*)d_in[i++];
        att[t] = (const float*)d_in[i++];
        bo[t]  = (const float*)d_in[i++];
    }
    const float* proj_W = (const float*)d_in[22];
    const float* proj_b = (const float*)d_in[23];
    const float* cls_W1 = (const float*)d_in[24];
    const float* cls_b1 = (const float*)d_in[25];
    const float* cls_W2 = (const float*)d_in[26];
    const float* cls_b2 = (const float*)d_in[27];
    const float* cls_W3 = (const float*)d_in[28];
    const float* cls_b3 = (const float*)d_in[29];
    float* out = (float*)d_out;

    const int SMEM_K4 = (11400 + 76 + 2250 + 30 + 60 + 2 + 150) * 4;  // 55872 B
    cudaFuncSetAttribute(k4, cudaFuncAttributeMaxDynamicSharedMemorySize, SMEM_K4);

    const int FOLDB = (150 * 76 + 76 + 255) / 256;   // 45

    k_pre<<<HB + 1, 256>>>(eis[0], eis[1], eis[2], att[0], att[1], att[2]); // 0
    k_scanA<<<NSB, SBLK>>>();                                               // 1
    k_scanBC<<<NSB, SBLK>>>();                                              // 2
    k_scatter<<<HB + FOLDB, 256>>>(eis[0], eis[1], eis[2],
                                   proj_W, proj_b, cls_W1, cls_b1);         // 3 <- profiled
    k1<<<(NN + 127) / 128, 128>>>(x,
                                  Wl[0], bl[0], Wr[0], br[0],
                                  Wl[1], bl[1], Wr[1], br[1],
                                  Wl[2], bl[2], Wr[2], br[2]);              // 4
    k_agg<<<(N3 * 32 + 255) / 256, 256>>>();                                // 5
    k4<<<(NN + K4N - 1) / K4N, K4N, SMEM_K4>>>(bo[0], bo[1], bo[2],
                                               cls_W2, cls_b2, cls_W3, cls_b3, out); // 6
}